// round 4
// baseline (speedup 1.0000x reference)
#include <cuda_runtime.h>
#include <cuda_bf16.h>

// EdgeDecoder: per-edge bilinear scores over 5 relations + softmax-expected rating.
//   z_user  [100000, 64] f32
//   z_movie [ 50000, 64] f32
//   rel_emb [     5, 64] f32
//   edge_label_index [2, E] int (32 or 64 — detected at runtime)
//   out [E] f32
//
// R4: profile shows nothing saturated (L1 64%, issue 54%, occ 49%) ->
// latency-exposed. Fixes:
//  - 16 lanes/edge: relD registers drop 32 -> 16, gathers still 256B-coalesced.
//  - 2 edges per loop iteration: 4 outstanding 128B gathers per thread (2x MLP).
//  - softmax shift trick retained (relD[r]=rel[r+1]-rel[0], score'[0]=0).

constexpr int H = 64;

__device__ int   g_idx_is64;
__device__ float g_relD[4 * H];   // rel[r+1][h] - rel[0][h]

__global__ void prep_kernel(const float* __restrict__ rel_emb,
                            const void* __restrict__ edge_idx) {
    const int t = threadIdx.x;
    if (t < 4 * H) {
        const int r = t >> 6, h = t & 63;
        g_relD[t] = rel_emb[(r + 1) * H + h] - rel_emb[h];
    }
    if (t == 0) {
        // int64-vs-int32 index detection: true int64 indices are all in
        // [0, 50000). int32 data reinterpreted as int64 gives lo + hi*2^32
        // with hi ~ U[0,50000): passing all 8 checks is ~impossible.
        const long long* p = (const long long*)edge_idx;
        int is64 = 1;
        #pragma unroll
        for (int i = 0; i < 8; i++) {
            long long v = p[i];
            if (v < 0 || v >= 50000) is64 = 0;
        }
        g_idx_is64 = is64;
    }
}

__global__ __launch_bounds__(256) void edge_decoder_kernel(
    const float* __restrict__ z_user,
    const float* __restrict__ z_movie,
    const void* __restrict__ edge_idx,
    float* __restrict__ out,
    int E)
{
    const int tid     = blockIdx.x * blockDim.x + threadIdx.x;
    const int sub     = threadIdx.x & 15;                // lane within 16-lane group
    const int ngroups = (gridDim.x * blockDim.x) >> 4;   // total edge groups
    const int g0      = tid >> 4;

    // relD slice for this lane: 4 relations x 1 float4. Loaded once; 16 regs.
    float4 rd[4];
    #pragma unroll
    for (int r = 0; r < 4; r++)
        rd[r] = *reinterpret_cast<const float4*>(g_relD + r * H + 4 * sub);

    const int is64 = g_idx_is64;
    const long long* p64 = (const long long*)edge_idx;
    const int*       p32 = (const int*)edge_idx;

    for (int e = g0; e < E; e += 2 * ngroups) {
        const int e2 = e + ngroups;
        const bool has2 = (e2 < E);

        // ---- issue ALL loads first (indices, then 4 gather float4s) ----
        long long sA, dA, sB = 0, dB = 0;
        if (is64) {
            sA = __ldg(p64 + e);
            dA = __ldg(p64 + (long long)E + e);
            if (has2) { sB = __ldg(p64 + e2); dB = __ldg(p64 + (long long)E + e2); }
        } else {
            sA = __ldg(p32 + e);
            dA = __ldg(p32 + E + e);
            if (has2) { sB = __ldg(p32 + e2); dB = __ldg(p32 + E + e2); }
        }

        const float4 uA = *reinterpret_cast<const float4*>(z_user  + sA * H + 4 * sub);
        const float4 mA = *reinterpret_cast<const float4*>(z_movie + dA * H + 4 * sub);
        float4 uB, mB;
        if (has2) {
            uB = *reinterpret_cast<const float4*>(z_user  + sB * H + 4 * sub);
            mB = *reinterpret_cast<const float4*>(z_movie + dB * H + 4 * sub);
        } else {
            uB = make_float4(0.f, 0.f, 0.f, 0.f);
            mB = uB;
        }

        // ---- compute both edges ----
        const float a0 = uA.x * mA.x, a1 = uA.y * mA.y,
                    a2 = uA.z * mA.z, a3 = uA.w * mA.w;
        const float b0 = uB.x * mB.x, b1 = uB.y * mB.y,
                    b2 = uB.z * mB.z, b3 = uB.w * mB.w;

        float scA[4], scB[4];
        #pragma unroll
        for (int r = 0; r < 4; r++) {
            scA[r] = fmaf(a0, rd[r].x, fmaf(a1, rd[r].y,
                     fmaf(a2, rd[r].z,      a3 * rd[r].w)));
            scB[r] = fmaf(b0, rd[r].x, fmaf(b1, rd[r].y,
                     fmaf(b2, rd[r].z,      b3 * rd[r].w)));
        }

        // Butterfly reduce across the 16-lane group; interleave A/B for ILP.
        #pragma unroll
        for (int off = 8; off >= 1; off >>= 1) {
            #pragma unroll
            for (int r = 0; r < 4; r++) {
                scA[r] += __shfl_xor_sync(0xffffffffu, scA[r], off);
                scB[r] += __shfl_xor_sync(0xffffffffu, scB[r], off);
            }
        }

        if (sub == 0) {
            {   // edge A: score'[0]=0, score'[r+1]=scA[r]
                float m = 0.f;
                #pragma unroll
                for (int r = 0; r < 4; r++) m = fmaxf(m, scA[r]);
                float den = __expf(-m), num = 0.f;
                #pragma unroll
                for (int r = 0; r < 4; r++) {
                    const float ex = __expf(scA[r] - m);
                    den += ex;
                    num = fmaf(ex, (float)(r + 1), num);
                }
                out[e] = num / den;
            }
            if (has2) {   // edge B
                float m = 0.f;
                #pragma unroll
                for (int r = 0; r < 4; r++) m = fmaxf(m, scB[r]);
                float den = __expf(-m), num = 0.f;
                #pragma unroll
                for (int r = 0; r < 4; r++) {
                    const float ex = __expf(scB[r] - m);
                    den += ex;
                    num = fmaf(ex, (float)(r + 1), num);
                }
                out[e2] = num / den;
            }
        }
    }
}

extern "C" void kernel_launch(void* const* d_in, const int* in_sizes, int n_in,
                              void* d_out, int out_size) {
    const float* z_user  = (const float*)d_in[0];
    const float* z_movie = (const float*)d_in[1];
    const float* rel_emb = (const float*)d_in[2];
    const void*  eidx    = d_in[3];
    float* out = (float*)d_out;

    const int E = out_size;  // one rating per edge

    prep_kernel<<<1, 256>>>(rel_emb, eidx);

    // Grid-stride persistent-ish grid: 8 CTAs/SM nominal on 152 SMs.
    const int threads = 256;
    const int blocks  = 152 * 8;
    edge_decoder_kernel<<<blocks, threads>>>(z_user, z_movie, eidx, out, E);
}